// round 1
// baseline (speedup 1.0000x reference)
#include <cuda_runtime.h>
#include <cuda_fp16.h>
#include <cstdint>

#define NB     16
#define NMEDIA 4096
#define NLAT   64
#define NKV    4160
#define DIM    1024
#define INNER  1024
#define NHEADS 16
#define DHEAD  64

// ---------------- scratch (static device globals; no runtime allocation) ----------------
__device__ __half g_kvin [(size_t)NB*NKV*DIM];      // layernormed [x ; latents]  (fp16)
__device__ __half g_lat16[(size_t)NB*NLAT*DIM];     // layernormed latents        (fp16)
__device__ __half g_q16  [(size_t)NB*NLAT*INNER];   // q * scale                  (fp16)
__device__ __half g_kv16 [(size_t)NB*NKV*2*INNER];  // [k | v]                    (fp16)
__device__ __half g_ao16 [(size_t)NB*NLAT*INNER];   // attention output           (fp16)
__device__ __half g_wq16 [(size_t)DIM*INNER];
__device__ __half g_wkv16[(size_t)DIM*2*INNER];
__device__ __half g_wout16[(size_t)INNER*DIM];

// ---------------- weight conversion fp32 -> fp16 ----------------
__global__ void cvt_weights(const float* __restrict__ Wq,
                            const float* __restrict__ Wkv,
                            const float* __restrict__ Wout) {
    int i = blockIdx.x * blockDim.x + threadIdx.x;
    const int n1 = DIM*INNER;        // 1M
    const int n2 = DIM*2*INNER;      // 2M
    const int n3 = INNER*DIM;        // 1M
    if (i < n1) g_wq16[i] = __float2half(Wq[i]);
    int j = i - n1;
    if (j >= 0 && j < n2) g_wkv16[j] = __float2half(Wkv[j]);
    int k = j - n2;
    if (k >= 0 && k < n3) g_wout16[k] = __float2half(Wout[k]);
}

// ---------------- fused layernorm (x and latents), writes fp16 ----------------
__global__ void __launch_bounds__(256) ln_kernel(
    const float* __restrict__ x, const float* __restrict__ lat,
    const float* __restrict__ gm, const float* __restrict__ bm,
    const float* __restrict__ gl, const float* __restrict__ bl)
{
    int r  = blockIdx.x;            // 0 .. NB*NKV-1
    int b  = r / NKV;
    int jj = r - b * NKV;
    bool isl = (jj >= NMEDIA);
    const float* src = isl ? lat + ((size_t)b*NLAT + (jj - NMEDIA))*DIM
                           : x   + ((size_t)b*NMEDIA + jj)*DIM;
    const float* g  = isl ? gl : gm;
    const float* be = isl ? bl : bm;

    int t = threadIdx.x;
    float v[4];
    float s = 0.f, s2 = 0.f;
#pragma unroll
    for (int k = 0; k < 4; k++) {
        float u = src[t + 256*k];
        v[k] = u; s += u; s2 += u*u;
    }
#pragma unroll
    for (int o = 16; o; o >>= 1) {
        s  += __shfl_xor_sync(0xffffffffu, s,  o);
        s2 += __shfl_xor_sync(0xffffffffu, s2, o);
    }
    __shared__ float rs[8], rs2[8];
    if ((t & 31) == 0) { rs[t >> 5] = s; rs2[t >> 5] = s2; }
    __syncthreads();
    float ts = 0.f, ts2 = 0.f;
#pragma unroll
    for (int w = 0; w < 8; w++) { ts += rs[w]; ts2 += rs2[w]; }
    float mu  = ts * (1.f/DIM);
    float inv = rsqrtf(ts2 * (1.f/DIM) - mu*mu + 1e-5f);

    __half* d1 = g_kvin + (size_t)r * DIM;
    __half* d2 = isl ? g_lat16 + ((size_t)b*NLAT + (jj - NMEDIA))*DIM : nullptr;
#pragma unroll
    for (int k = 0; k < 4; k++) {
        int c = t + 256*k;
        __half hv = __float2half((v[k] - mu) * inv * g[c] + be[c]);
        d1[c] = hv;
        if (d2) d2[c] = hv;
    }
}

// ---------------- fp16 tensor-core GEMM:  C[M,N] = alpha * A[M,K] @ B[K,N] ----------------
// A,B row-major fp16. BM=BN=128, BK=32, 256 threads (8 warps, 2x4), warp tile 64x32.
#define BM 128
#define BN 128
#define BK 32

template<typename OutT>
__global__ void __launch_bounds__(256, 2) gemm_h16(
    const __half* __restrict__ A, const __half* __restrict__ Bmat,
    OutT* __restrict__ C, int M, int N, int K, float alpha)
{
    __shared__ __half As[BM][BK + 8];    // stride 40 halves (80B): conflict-free ldmatrix
    __shared__ __half Bs[BK][BN + 8];    // stride 136 halves (272B)

    const int tid  = threadIdx.x;
    const int warp = tid >> 5, lane = tid & 31;
    const int wm = (warp & 1) * 64;
    const int wn = (warp >> 1) * 32;
    const int bm0 = blockIdx.y * BM;
    const int bn0 = blockIdx.x * BN;

    float acc[4][4][4];
#pragma unroll
    for (int a = 0; a < 4; a++)
#pragma unroll
        for (int b = 0; b < 4; b++)
#pragma unroll
            for (int c = 0; c < 4; c++) acc[a][b][c] = 0.f;

    const int arow = tid >> 2, acol = (tid & 3) * 8;    // A tile: 128 x 32
    const int brow = tid >> 4, bcol = (tid & 15) * 8;   // B tile: 32 x 128

    for (int k0 = 0; k0 < K; k0 += BK) {
        const __half* ga = A + (size_t)(bm0 + arow) * K + (k0 + acol);
        *(uint4*)(&As[arow     ][acol]) = *(const uint4*)ga;
        *(uint4*)(&As[arow + 64][acol]) = *(const uint4*)(ga + (size_t)64 * K);
        const __half* gb = Bmat + (size_t)(k0 + brow) * N + (bn0 + bcol);
        *(uint4*)(&Bs[brow     ][bcol]) = *(const uint4*)gb;
        *(uint4*)(&Bs[brow + 16][bcol]) = *(const uint4*)(gb + (size_t)16 * N);
        __syncthreads();

#pragma unroll
        for (int kc = 0; kc < BK; kc += 16) {
            uint32_t af[4][4], bf[4][2];
#pragma unroll
            for (int mf = 0; mf < 4; mf++) {
                uint32_t ad = (uint32_t)__cvta_generic_to_shared(
                    &As[wm + mf*16 + (lane & 15)][kc + ((lane >> 4) << 3)]);
                asm volatile("ldmatrix.sync.aligned.m8n8.x4.shared.b16 {%0,%1,%2,%3}, [%4];"
                    : "=r"(af[mf][0]), "=r"(af[mf][1]), "=r"(af[mf][2]), "=r"(af[mf][3])
                    : "r"(ad));
            }
#pragma unroll
            for (int nf = 0; nf < 4; nf++) {
                uint32_t bd = (uint32_t)__cvta_generic_to_shared(
                    &Bs[kc + (lane & 15)][wn + nf*8]);
                asm volatile("ldmatrix.sync.aligned.m8n8.x2.trans.shared.b16 {%0,%1}, [%2];"
                    : "=r"(bf[nf][0]), "=r"(bf[nf][1]) : "r"(bd));
            }
#pragma unroll
            for (int mf = 0; mf < 4; mf++)
#pragma unroll
                for (int nf = 0; nf < 4; nf++) {
                    asm volatile(
                        "mma.sync.aligned.m16n8k16.row.col.f32.f16.f16.f32 "
                        "{%0,%1,%2,%3}, {%4,%5,%6,%7}, {%8,%9}, {%0,%1,%2,%3};"
                        : "+f"(acc[mf][nf][0]), "+f"(acc[mf][nf][1]),
                          "+f"(acc[mf][nf][2]), "+f"(acc[mf][nf][3])
                        : "r"(af[mf][0]), "r"(af[mf][1]), "r"(af[mf][2]), "r"(af[mf][3]),
                          "r"(bf[nf][0]), "r"(bf[nf][1]));
                }
        }
        __syncthreads();
    }

    const int grp = lane >> 2, tig = lane & 3;
#pragma unroll
    for (int mf = 0; mf < 4; mf++)
#pragma unroll
        for (int nf = 0; nf < 4; nf++) {
            int row = bm0 + wm + mf*16 + grp;
            int col = bn0 + wn + nf*8 + tig*2;
            if constexpr (sizeof(OutT) == 2) {
                *(__half2*)&C[(size_t)row * N + col] =
                    __floats2half2_rn(acc[mf][nf][0]*alpha, acc[mf][nf][1]*alpha);
                *(__half2*)&C[(size_t)(row + 8) * N + col] =
                    __floats2half2_rn(acc[mf][nf][2]*alpha, acc[mf][nf][3]*alpha);
            } else {
                *(float2*)&C[(size_t)row * N + col] =
                    make_float2(acc[mf][nf][0]*alpha, acc[mf][nf][1]*alpha);
                *(float2*)&C[(size_t)(row + 8) * N + col] =
                    make_float2(acc[mf][nf][2]*alpha, acc[mf][nf][3]*alpha);
            }
        }
}

// ---------------- flash attention: one CTA per (b, h) ----------------
// Q tile 64x64, stream K/V in 64-row tiles, online softmax, fp32 accum.
// smem strides 65 (== 1 mod 32) keep row accesses conflict-free.
#define ATTN_SMEM ((3*64*65 + 64*64) * (int)sizeof(float))

__global__ void __launch_bounds__(256) attn_kernel() {
    extern __shared__ float smf[];
    float* Qs = smf;               // 64 x 65
    float* Ks = Qs + 64*65;
    float* Vs = Ks + 64*65;
    float* Ps = Vs + 64*65;        // 64 x 64

    const int b = blockIdx.x, h = blockIdx.y;
    const int tid = threadIdx.x;
    const int ig = tid >> 4;       // 0..15 -> 4 rows each
    const int jt = tid & 15;       // 0..15 -> j/d lanes

    // load Q (fp16 -> fp32)
    {
        int i = tid >> 2, d0 = (tid & 3) * 16;
        const __half2* q = (const __half2*)(g_q16 + ((size_t)(b*NLAT + i))*INNER + h*DHEAD + d0);
#pragma unroll
        for (int k = 0; k < 8; k++) {
            float2 f = __half22float2(q[k]);
            Qs[i*65 + d0 + 2*k]     = f.x;
            Qs[i*65 + d0 + 2*k + 1] = f.y;
        }
    }

    float m[4], l[4], Ob[4][4];
#pragma unroll
    for (int a = 0; a < 4; a++) {
        m[a] = -1e30f; l[a] = 0.f;
#pragma unroll
        for (int c = 0; c < 4; c++) Ob[a][c] = 0.f;
    }

    const int ldrow = tid >> 2, ldc = (tid & 3) * 16;

    for (int j0 = 0; j0 < NKV; j0 += 64) {
        __syncthreads();   // protects Qs (first iter) and Ks/Vs from previous readers
        {
            const size_t base = ((size_t)(b*NKV + j0 + ldrow)) * (2*INNER) + h*DHEAD + ldc;
            const __half2* kp = (const __half2*)(g_kv16 + base);
            const __half2* vp = (const __half2*)(g_kv16 + base + INNER);
#pragma unroll
            for (int k = 0; k < 8; k++) {
                float2 f  = __half22float2(kp[k]);
                float2 f2 = __half22float2(vp[k]);
                Ks[ldrow*65 + ldc + 2*k]     = f.x;
                Ks[ldrow*65 + ldc + 2*k + 1] = f.y;
                Vs[ldrow*65 + ldc + 2*k]     = f2.x;
                Vs[ldrow*65 + ldc + 2*k + 1] = f2.y;
            }
        }
        __syncthreads();

        // S = Q @ K^T  (4x4 register tile per thread)
        float sacc[4][4];
#pragma unroll
        for (int a = 0; a < 4; a++)
#pragma unroll
            for (int c = 0; c < 4; c++) sacc[a][c] = 0.f;

        for (int d = 0; d < 64; d++) {
            float qv[4], kv[4];
#pragma unroll
            for (int a = 0; a < 4; a++) qv[a] = Qs[(ig*4 + a)*65 + d];
#pragma unroll
            for (int c = 0; c < 4; c++) kv[c] = Ks[(jt + 16*c)*65 + d];
#pragma unroll
            for (int a = 0; a < 4; a++)
#pragma unroll
                for (int c = 0; c < 4; c++) sacc[a][c] += qv[a] * kv[c];
        }

        // online softmax per row (reduction across the 16 jt lanes of this ig group)
#pragma unroll
        for (int a = 0; a < 4; a++) {
            float tm = fmaxf(fmaxf(sacc[a][0], sacc[a][1]), fmaxf(sacc[a][2], sacc[a][3]));
#pragma unroll
            for (int o = 8; o; o >>= 1) tm = fmaxf(tm, __shfl_xor_sync(0xffffffffu, tm, o));
            float mn   = fmaxf(m[a], tm);
            float corr = __expf(m[a] - mn);
            float ls = 0.f;
#pragma unroll
            for (int c = 0; c < 4; c++) {
                float p = __expf(sacc[a][c] - mn);
                Ps[(ig*4 + a)*64 + jt + 16*c] = p;
                ls += p;
            }
#pragma unroll
            for (int o = 8; o; o >>= 1) ls += __shfl_xor_sync(0xffffffffu, ls, o);
            l[a] = l[a] * corr + ls;
            m[a] = mn;
#pragma unroll
            for (int c = 0; c < 4; c++) Ob[a][c] *= corr;
        }
        __syncthreads();

        // O += P @ V
        for (int jl = 0; jl < 64; jl++) {
            float vv[4], pv[4];
#pragma unroll
            for (int c = 0; c < 4; c++) vv[c] = Vs[jl*65 + jt + 16*c];
#pragma unroll
            for (int a = 0; a < 4; a++) pv[a] = Ps[(ig*4 + a)*64 + jl];
#pragma unroll
            for (int a = 0; a < 4; a++)
#pragma unroll
                for (int c = 0; c < 4; c++) Ob[a][c] += pv[a] * vv[c];
        }
    }

    // write attention output (fp16)
#pragma unroll
    for (int a = 0; a < 4; a++) {
        float inv = 1.f / l[a];
        int row = b*NLAT + ig*4 + a;
#pragma unroll
        for (int c = 0; c < 4; c++) {
            g_ao16[(size_t)row * INNER + h*DHEAD + jt + 16*c] = __float2half(Ob[a][c] * inv);
        }
    }
}

// ---------------- launch ----------------
extern "C" void kernel_launch(void* const* d_in, const int* in_sizes, int n_in,
                              void* d_out, int out_size) {
    const float* x    = (const float*)d_in[0];
    const float* lat  = (const float*)d_in[1];
    const float* gm   = (const float*)d_in[2];
    const float* bm   = (const float*)d_in[3];
    const float* gl   = (const float*)d_in[4];
    const float* bl   = (const float*)d_in[5];
    const float* Wq   = (const float*)d_in[6];
    const float* Wkv  = (const float*)d_in[7];
    const float* Wout = (const float*)d_in[8];
    float* out = (float*)d_out;

    // scratch symbol addresses (query only; no allocation)
    void *p_kvin, *p_lat, *p_q, *p_kv, *p_ao, *p_wq, *p_wkv, *p_wout;
    cudaGetSymbolAddress(&p_kvin, g_kvin);
    cudaGetSymbolAddress(&p_lat,  g_lat16);
    cudaGetSymbolAddress(&p_q,    g_q16);
    cudaGetSymbolAddress(&p_kv,   g_kv16);
    cudaGetSymbolAddress(&p_ao,   g_ao16);
    cudaGetSymbolAddress(&p_wq,   g_wq16);
    cudaGetSymbolAddress(&p_wkv,  g_wkv16);
    cudaGetSymbolAddress(&p_wout, g_wout16);

    cudaFuncSetAttribute(attn_kernel, cudaFuncAttributeMaxDynamicSharedMemorySize, ATTN_SMEM);

    // 1. weights fp32 -> fp16
    cvt_weights<<<(4*1024*1024 + 255)/256, 256>>>(Wq, Wkv, Wout);

    // 2. layernorm x + latents -> fp16 concat buffer + latent buffer
    ln_kernel<<<NB*NKV, 256>>>(x, lat, gm, bm, gl, bl);

    // 3. q = lat_ln @ Wq * d^-0.5   [1024, 1024]
    {
        dim3 grid(INNER/BN, (NB*NLAT)/BM);
        gemm_h16<__half><<<grid, 256>>>((const __half*)p_lat, (const __half*)p_wq,
                                        (__half*)p_q, NB*NLAT, INNER, DIM, 0.125f);
    }

    // 4. kv = [x_ln ; lat_ln] @ Wkv   [66560, 2048]
    {
        dim3 grid((2*INNER)/BN, (NB*NKV)/BM);
        gemm_h16<__half><<<grid, 256>>>((const __half*)p_kvin, (const __half*)p_wkv,
                                        (__half*)p_kv, NB*NKV, 2*INNER, DIM, 1.0f);
    }

    // 5. attention per (b, h)
    {
        dim3 grid(NB, NHEADS);
        attn_kernel<<<grid, 256, ATTN_SMEM>>>();
    }

    // 6. out = ao @ Wout   [1024, 1024] fp32 -> d_out
    {
        dim3 grid(DIM/BN, (NB*NLAT)/BM);
        gemm_h16<float><<<grid, 256>>>((const __half*)p_ao, (const __half*)p_wout,
                                       out, NB*NLAT, DIM, INNER, 1.0f);
    }
}

// round 2
// speedup vs baseline: 1.2282x; 1.2282x over previous
#include <cuda_runtime.h>
#include <cuda_fp16.h>
#include <cstdint>

#define NB     16
#define NMEDIA 4096
#define NLAT   64
#define NKV    4160
#define DIM    1024
#define INNER  1024
#define NHEADS 16
#define DHEAD  64

// ---------------- scratch (static device globals; no runtime allocation) ----------------
__device__ __half g_kvin [(size_t)NB*NKV*DIM];      // layernormed [x ; latents]  (fp16)
__device__ __half g_lat16[(size_t)NB*NLAT*DIM];     // layernormed latents        (fp16)
__device__ __half g_q16  [(size_t)NB*NLAT*INNER];   // q * scale                  (fp16)
__device__ __half g_kv16 [(size_t)NB*NKV*2*INNER];  // [k | v]                    (fp16)
__device__ __half g_ao16 [(size_t)NB*NLAT*INNER];   // attention output           (fp16)
__device__ __half g_wq16 [(size_t)DIM*INNER];
__device__ __half g_wkv16[(size_t)DIM*2*INNER];
__device__ __half g_wout16[(size_t)INNER*DIM];

// ---------------- helpers ----------------
__device__ __forceinline__ void cp_async16(uint32_t smem_dst, const void* gsrc) {
    asm volatile("cp.async.cg.shared.global [%0], [%1], 16;\n" :: "r"(smem_dst), "l"(gsrc));
}
__device__ __forceinline__ void cp_commit() {
    asm volatile("cp.async.commit_group;\n" ::);
}
__device__ __forceinline__ void cp_wait1() {
    asm volatile("cp.async.wait_group 1;\n" ::);
}
__device__ __forceinline__ void cp_wait0() {
    asm volatile("cp.async.wait_group 0;\n" ::);
}

// ---------------- weight conversion fp32 -> fp16 ----------------
__global__ void cvt_weights(const float* __restrict__ Wq,
                            const float* __restrict__ Wkv,
                            const float* __restrict__ Wout) {
    int i = blockIdx.x * blockDim.x + threadIdx.x;
    const int n1 = DIM*INNER;
    const int n2 = DIM*2*INNER;
    const int n3 = INNER*DIM;
    if (i < n1) g_wq16[i] = __float2half(Wq[i]);
    int j = i - n1;
    if (j >= 0 && j < n2) g_wkv16[j] = __float2half(Wkv[j]);
    int k = j - n2;
    if (k >= 0 && k < n3) g_wout16[k] = __float2half(Wout[k]);
}

// ---------------- fused layernorm (x and latents), writes fp16 ----------------
__global__ void __launch_bounds__(256) ln_kernel(
    const float* __restrict__ x, const float* __restrict__ lat,
    const float* __restrict__ gm, const float* __restrict__ bm,
    const float* __restrict__ gl, const float* __restrict__ bl)
{
    int r  = blockIdx.x;            // 0 .. NB*NKV-1
    int b  = r / NKV;
    int jj = r - b * NKV;
    bool isl = (jj >= NMEDIA);
    const float* src = isl ? lat + ((size_t)b*NLAT + (jj - NMEDIA))*DIM
                           : x   + ((size_t)b*NMEDIA + jj)*DIM;
    const float* g  = isl ? gl : gm;
    const float* be = isl ? bl : bm;

    int t = threadIdx.x;
    float v[4];
    float s = 0.f, s2 = 0.f;
#pragma unroll
    for (int k = 0; k < 4; k++) {
        float u = src[t + 256*k];
        v[k] = u; s += u; s2 += u*u;
    }
#pragma unroll
    for (int o = 16; o; o >>= 1) {
        s  += __shfl_xor_sync(0xffffffffu, s,  o);
        s2 += __shfl_xor_sync(0xffffffffu, s2, o);
    }
    __shared__ float rs[8], rs2[8];
    if ((t & 31) == 0) { rs[t >> 5] = s; rs2[t >> 5] = s2; }
    __syncthreads();
    float ts = 0.f, ts2 = 0.f;
#pragma unroll
    for (int w = 0; w < 8; w++) { ts += rs[w]; ts2 += rs2[w]; }
    float mu  = ts * (1.f/DIM);
    float inv = rsqrtf(ts2 * (1.f/DIM) - mu*mu + 1e-5f);

    __half* d1 = g_kvin + (size_t)r * DIM;
    __half* d2 = isl ? g_lat16 + ((size_t)b*NLAT + (jj - NMEDIA))*DIM : nullptr;
#pragma unroll
    for (int k = 0; k < 4; k++) {
        int c = t + 256*k;
        __half hv = __float2half((v[k] - mu) * inv * g[c] + be[c]);
        d1[c] = hv;
        if (d2) d2[c] = hv;
    }
}

// ---------------- double-buffered fp16 tensor-core GEMM ----------------
// C[M,N] = alpha * A[M,K] @ B[K,N].  BM=BN=128, BK=64, 256 threads, cp.async pipeline.
#define BM 128
#define BN 128
#define BKG 64
#define AS_STRIDE 72
#define BS_STRIDE 136
// dynamic smem: As[2][128][72] halves then Bs[2][64][136] halves
#define GEMM_SMEM ((2*BM*AS_STRIDE + 2*BKG*BS_STRIDE) * (int)sizeof(__half))

template<typename OutT>
__global__ void __launch_bounds__(256) gemm_db(
    const __half* __restrict__ A, const __half* __restrict__ Bmat,
    OutT* __restrict__ C, int M, int N, int K, float alpha)
{
    extern __shared__ __half smh[];
    __half* As = smh;                          // [2][BM][AS_STRIDE]
    __half* Bs = smh + 2*BM*AS_STRIDE;         // [2][BKG][BS_STRIDE]

    const int tid  = threadIdx.x;
    const int warp = tid >> 5, lane = tid & 31;
    const int wm = (warp & 1) * 64;
    const int wn = (warp >> 1) * 32;
    const int bm0 = blockIdx.y * BM;
    const int bn0 = blockIdx.x * BN;

    float acc[4][4][4];
#pragma unroll
    for (int a = 0; a < 4; a++)
#pragma unroll
        for (int b = 0; b < 4; b++)
#pragma unroll
            for (int c = 0; c < 4; c++) acc[a][b][c] = 0.f;

    // load mapping
    const int arow = tid >> 1, acb = (tid & 1) * 32;   // A tile 128 x 64
    const int brow = tid >> 2, bcb = (tid & 3) * 32;   // B tile 64 x 128

    const uint32_t sA = (uint32_t)__cvta_generic_to_shared(As);
    const uint32_t sB = (uint32_t)__cvta_generic_to_shared(Bs);

    auto issue = [&](int k0, int st) {
        const __half* ga = A + (size_t)(bm0 + arow) * K + (k0 + acb);
        uint32_t da = sA + ((st*BM + arow)*AS_STRIDE + acb) * 2;
#pragma unroll
        for (int c = 0; c < 4; c++) cp_async16(da + c*16, ga + c*8);
        const __half* gb = Bmat + (size_t)(k0 + brow) * N + (bn0 + bcb);
        uint32_t db = sB + ((st*BKG + brow)*BS_STRIDE + bcb) * 2;
#pragma unroll
        for (int c = 0; c < 4; c++) cp_async16(db + c*16, gb + c*8);
    };

    issue(0, 0);
    cp_commit();

    int stage = 0;
    for (int k0 = 0; k0 < K; k0 += BKG) {
        if (k0 + BKG < K) { issue(k0 + BKG, stage ^ 1); cp_commit(); cp_wait1(); }
        else              { cp_wait0(); }
        __syncthreads();

        const __half* as = As + (size_t)stage * BM * AS_STRIDE;
        const __half* bs = Bs + (size_t)stage * BKG * BS_STRIDE;

#pragma unroll
        for (int kc = 0; kc < BKG; kc += 16) {
            uint32_t af[4][4], bf[4][2];
#pragma unroll
            for (int mf = 0; mf < 4; mf++) {
                uint32_t ad = (uint32_t)__cvta_generic_to_shared(
                    &as[(wm + mf*16 + (lane & 15))*AS_STRIDE + kc + ((lane >> 4) << 3)]);
                asm volatile("ldmatrix.sync.aligned.m8n8.x4.shared.b16 {%0,%1,%2,%3}, [%4];"
                    : "=r"(af[mf][0]), "=r"(af[mf][1]), "=r"(af[mf][2]), "=r"(af[mf][3])
                    : "r"(ad));
            }
#pragma unroll
            for (int nf = 0; nf < 4; nf++) {
                uint32_t bd = (uint32_t)__cvta_generic_to_shared(
                    &bs[(kc + (lane & 15))*BS_STRIDE + wn + nf*8]);
                asm volatile("ldmatrix.sync.aligned.m8n8.x2.trans.shared.b16 {%0,%1}, [%2];"
                    : "=r"(bf[nf][0]), "=r"(bf[nf][1]) : "r"(bd));
            }
#pragma unroll
            for (int mf = 0; mf < 4; mf++)
#pragma unroll
                for (int nf = 0; nf < 4; nf++) {
                    asm volatile(
                        "mma.sync.aligned.m16n8k16.row.col.f32.f16.f16.f32 "
                        "{%0,%1,%2,%3}, {%4,%5,%6,%7}, {%8,%9}, {%0,%1,%2,%3};"
                        : "+f"(acc[mf][nf][0]), "+f"(acc[mf][nf][1]),
                          "+f"(acc[mf][nf][2]), "+f"(acc[mf][nf][3])
                        : "r"(af[mf][0]), "r"(af[mf][1]), "r"(af[mf][2]), "r"(af[mf][3]),
                          "r"(bf[nf][0]), "r"(bf[nf][1]));
                }
        }
        __syncthreads();
        stage ^= 1;
    }

    const int grp = lane >> 2, tig = lane & 3;
#pragma unroll
    for (int mf = 0; mf < 4; mf++)
#pragma unroll
        for (int nf = 0; nf < 4; nf++) {
            int row = bm0 + wm + mf*16 + grp;
            int col = bn0 + wn + nf*8 + tig*2;
            if constexpr (sizeof(OutT) == 2) {
                *(__half2*)&C[(size_t)row * N + col] =
                    __floats2half2_rn(acc[mf][nf][0]*alpha, acc[mf][nf][1]*alpha);
                *(__half2*)&C[(size_t)(row + 8) * N + col] =
                    __floats2half2_rn(acc[mf][nf][2]*alpha, acc[mf][nf][3]*alpha);
            } else {
                *(float2*)&C[(size_t)row * N + col] =
                    make_float2(acc[mf][nf][0]*alpha, acc[mf][nf][1]*alpha);
                *(float2*)&C[(size_t)(row + 8) * N + col] =
                    make_float2(acc[mf][nf][2]*alpha, acc[mf][nf][3]*alpha);
            }
        }
}

// ---------------- tensor-core flash attention: one CTA per (b, h) ----------------
// 4 warps, each owns 16 Q rows. Q frags in registers; K/V double-buffered cp.async.
// Online softmax entirely in C-fragment registers.
#define QS_STR 72

__global__ void __launch_bounds__(128) attn_mma_kernel() {
    __shared__ __half Qs[64][QS_STR];
    __shared__ __half Ks[2][64][QS_STR];
    __shared__ __half Vs[2][64][QS_STR];

    const int b = blockIdx.x, h = blockIdx.y;
    const int tid = threadIdx.x;
    const int warp = tid >> 5, lane = tid & 31;
    const int grp = lane >> 2, tig = lane & 3;

    // ---- load Q tile (64 x 64 fp16) ----
    {
        int row = tid >> 1, cb = (tid & 1) * 32;
        const __half* q = g_q16 + ((size_t)(b*NLAT + row))*INNER + h*DHEAD + cb;
#pragma unroll
        for (int c = 0; c < 4; c++)
            *(uint4*)&Qs[row][cb + c*8] = *(const uint4*)(q + c*8);
    }
    __syncthreads();

    // Q fragments: 4 k-steps (d), m16k16 each
    uint32_t qf[4][4];
#pragma unroll
    for (int kk = 0; kk < 4; kk++) {
        uint32_t ad = (uint32_t)__cvta_generic_to_shared(
            &Qs[warp*16 + (lane & 15)][kk*16 + ((lane >> 4) << 3)]);
        asm volatile("ldmatrix.sync.aligned.m8n8.x4.shared.b16 {%0,%1,%2,%3}, [%4];"
            : "=r"(qf[kk][0]), "=r"(qf[kk][1]), "=r"(qf[kk][2]), "=r"(qf[kk][3])
            : "r"(ad));
    }

    const uint32_t sK = (uint32_t)__cvta_generic_to_shared(&Ks[0][0][0]);
    const uint32_t sV = (uint32_t)__cvta_generic_to_shared(&Vs[0][0][0]);
    const int ldr = tid >> 1, ldcb = (tid & 1) * 32;

    auto issue_kv = [&](int jt, int st) {
        size_t gbase = ((size_t)(b*NKV + jt*64 + ldr)) * (2*INNER) + h*DHEAD + ldcb;
        uint32_t dk = sK + ((st*64 + ldr)*QS_STR + ldcb) * 2;
        uint32_t dv = sV + ((st*64 + ldr)*QS_STR + ldcb) * 2;
#pragma unroll
        for (int c = 0; c < 4; c++) {
            cp_async16(dk + c*16, g_kv16 + gbase + c*8);
            cp_async16(dv + c*16, g_kv16 + gbase + INNER + c*8);
        }
    };

    issue_kv(0, 0);
    cp_commit();

    float m0 = -1e30f, m1 = -1e30f, l0 = 0.f, l1 = 0.f;
    float of[8][4];
#pragma unroll
    for (int nf = 0; nf < 8; nf++)
#pragma unroll
        for (int c = 0; c < 4; c++) of[nf][c] = 0.f;

    int stage = 0;
    for (int jt = 0; jt < NKV/64; jt++) {
        if (jt + 1 < NKV/64) { issue_kv(jt + 1, stage ^ 1); cp_commit(); cp_wait1(); }
        else                 { cp_wait0(); }
        __syncthreads();

        // ---- S = Q @ K^T ----
        float sf[8][4];
#pragma unroll
        for (int nf = 0; nf < 8; nf++) {
            sf[nf][0] = sf[nf][1] = sf[nf][2] = sf[nf][3] = 0.f;
#pragma unroll
            for (int kk = 0; kk < 4; kk++) {
                uint32_t bd = (uint32_t)__cvta_generic_to_shared(
                    &Ks[stage][nf*8 + (lane & 7)][kk*16 + ((lane >> 3) & 1) * 8]);
                uint32_t b0, b1;
                asm volatile("ldmatrix.sync.aligned.m8n8.x2.shared.b16 {%0,%1}, [%2];"
                    : "=r"(b0), "=r"(b1) : "r"(bd));
                asm volatile(
                    "mma.sync.aligned.m16n8k16.row.col.f32.f16.f16.f32 "
                    "{%0,%1,%2,%3}, {%4,%5,%6,%7}, {%8,%9}, {%0,%1,%2,%3};"
                    : "+f"(sf[nf][0]), "+f"(sf[nf][1]), "+f"(sf[nf][2]), "+f"(sf[nf][3])
                    : "r"(qf[kk][0]), "r"(qf[kk][1]), "r"(qf[kk][2]), "r"(qf[kk][3]),
                      "r"(b0), "r"(b1));
            }
        }

        // ---- online softmax (rows grp and grp+8) ----
        float mx0 = -1e30f, mx1 = -1e30f;
#pragma unroll
        for (int nf = 0; nf < 8; nf++) {
            mx0 = fmaxf(mx0, fmaxf(sf[nf][0], sf[nf][1]));
            mx1 = fmaxf(mx1, fmaxf(sf[nf][2], sf[nf][3]));
        }
        mx0 = fmaxf(mx0, __shfl_xor_sync(0xffffffffu, mx0, 1));
        mx0 = fmaxf(mx0, __shfl_xor_sync(0xffffffffu, mx0, 2));
        mx1 = fmaxf(mx1, __shfl_xor_sync(0xffffffffu, mx1, 1));
        mx1 = fmaxf(mx1, __shfl_xor_sync(0xffffffffu, mx1, 2));

        float mn0 = fmaxf(m0, mx0), mn1 = fmaxf(m1, mx1);
        float sc0 = __expf(m0 - mn0), sc1 = __expf(m1 - mn1);

        uint32_t pa[8], pb[8];
        float ls0 = 0.f, ls1 = 0.f;
#pragma unroll
        for (int nf = 0; nf < 8; nf++) {
            float p0 = __expf(sf[nf][0] - mn0);
            float p1 = __expf(sf[nf][1] - mn0);
            float p2 = __expf(sf[nf][2] - mn1);
            float p3 = __expf(sf[nf][3] - mn1);
            ls0 += p0 + p1; ls1 += p2 + p3;
            __half2 ha = __floats2half2_rn(p0, p1);
            __half2 hb = __floats2half2_rn(p2, p3);
            pa[nf] = *(uint32_t*)&ha;
            pb[nf] = *(uint32_t*)&hb;
        }
        ls0 += __shfl_xor_sync(0xffffffffu, ls0, 1);
        ls0 += __shfl_xor_sync(0xffffffffu, ls0, 2);
        ls1 += __shfl_xor_sync(0xffffffffu, ls1, 1);
        ls1 += __shfl_xor_sync(0xffffffffu, ls1, 2);

        l0 = l0 * sc0 + ls0;
        l1 = l1 * sc1 + ls1;
        m0 = mn0; m1 = mn1;
#pragma unroll
        for (int nf = 0; nf < 8; nf++) {
            of[nf][0] *= sc0; of[nf][1] *= sc0;
            of[nf][2] *= sc1; of[nf][3] *= sc1;
        }

        // ---- O += P @ V ----
#pragma unroll
        for (int nf = 0; nf < 8; nf++) {
#pragma unroll
            for (int kk = 0; kk < 4; kk++) {
                uint32_t bd = (uint32_t)__cvta_generic_to_shared(
                    &Vs[stage][kk*16 + (lane & 15)][nf*8]);
                uint32_t b0, b1;
                asm volatile("ldmatrix.sync.aligned.m8n8.x2.trans.shared.b16 {%0,%1}, [%2];"
                    : "=r"(b0), "=r"(b1) : "r"(bd));
                asm volatile(
                    "mma.sync.aligned.m16n8k16.row.col.f32.f16.f16.f32 "
                    "{%0,%1,%2,%3}, {%4,%5,%6,%7}, {%8,%9}, {%0,%1,%2,%3};"
                    : "+f"(of[nf][0]), "+f"(of[nf][1]), "+f"(of[nf][2]), "+f"(of[nf][3])
                    : "r"(pa[2*kk]), "r"(pb[2*kk]), "r"(pa[2*kk+1]), "r"(pb[2*kk+1]),
                      "r"(b0), "r"(b1));
            }
        }
        __syncthreads();
        stage ^= 1;
    }

    // ---- epilogue ----
    float inv0 = 1.f / l0, inv1 = 1.f / l1;
    int row0 = b*NLAT + warp*16 + grp;
#pragma unroll
    for (int nf = 0; nf < 8; nf++) {
        int col = h*DHEAD + nf*8 + tig*2;
        *(__half2*)&g_ao16[(size_t)row0 * INNER + col] =
            __floats2half2_rn(of[nf][0]*inv0, of[nf][1]*inv0);
        *(__half2*)&g_ao16[(size_t)(row0 + 8) * INNER + col] =
            __floats2half2_rn(of[nf][2]*inv1, of[nf][3]*inv1);
    }
}

// ---------------- launch ----------------
extern "C" void kernel_launch(void* const* d_in, const int* in_sizes, int n_in,
                              void* d_out, int out_size) {
    const float* x    = (const float*)d_in[0];
    const float* lat  = (const float*)d_in[1];
    const float* gm   = (const float*)d_in[2];
    const float* bm   = (const float*)d_in[3];
    const float* gl   = (const float*)d_in[4];
    const float* bl   = (const float*)d_in[5];
    const float* Wq   = (const float*)d_in[6];
    const float* Wkv  = (const float*)d_in[7];
    const float* Wout = (const float*)d_in[8];
    float* out = (float*)d_out;

    void *p_kvin, *p_lat, *p_q, *p_kv, *p_ao, *p_wq, *p_wkv, *p_wout;
    cudaGetSymbolAddress(&p_kvin, g_kvin);
    cudaGetSymbolAddress(&p_lat,  g_lat16);
    cudaGetSymbolAddress(&p_q,    g_q16);
    cudaGetSymbolAddress(&p_kv,   g_kv16);
    cudaGetSymbolAddress(&p_ao,   g_ao16);
    cudaGetSymbolAddress(&p_wq,   g_wq16);
    cudaGetSymbolAddress(&p_wkv,  g_wkv16);
    cudaGetSymbolAddress(&p_wout, g_wout16);

    static bool attr_done = false;
    if (!attr_done) {
        cudaFuncSetAttribute(gemm_db<__half>, cudaFuncAttributeMaxDynamicSharedMemorySize, GEMM_SMEM);
        cudaFuncSetAttribute(gemm_db<float>,  cudaFuncAttributeMaxDynamicSharedMemorySize, GEMM_SMEM);
        attr_done = true;
    }

    // 1. weights fp32 -> fp16
    cvt_weights<<<(4*1024*1024 + 255)/256, 256>>>(Wq, Wkv, Wout);

    // 2. layernorm x + latents -> fp16 concat buffer + latent buffer
    ln_kernel<<<NB*NKV, 256>>>(x, lat, gm, bm, gl, bl);

    // 3. q = lat_ln @ Wq * d^-0.5   [1024, 1024]
    {
        dim3 grid(INNER/BN, (NB*NLAT)/BM);
        gemm_db<__half><<<grid, 256, GEMM_SMEM>>>((const __half*)p_lat, (const __half*)p_wq,
                                                  (__half*)p_q, NB*NLAT, INNER, DIM, 0.125f);
    }

    // 4. kv = [x_ln ; lat_ln] @ Wkv   [66560, 2048]
    {
        dim3 grid((2*INNER)/BN, (NB*NKV)/BM);
        gemm_db<__half><<<grid, 256, GEMM_SMEM>>>((const __half*)p_kvin, (const __half*)p_wkv,
                                                  (__half*)p_kv, NB*NKV, 2*INNER, DIM, 1.0f);
    }

    // 5. attention per (b, h) — tensor-core flash attention
    {
        dim3 grid(NB, NHEADS);
        attn_mma_kernel<<<grid, 128>>>();
    }

    // 6. out = ao @ Wout   [1024, 1024] fp32 -> d_out
    {
        dim3 grid(DIM/BN, (NB*NLAT)/BM);
        gemm_db<float><<<grid, 256, GEMM_SMEM>>>((const __half*)p_ao, (const __half*)p_wout,
                                                 out, NB*NLAT, DIM, INNER, 1.0f);
    }
}

// round 4
// speedup vs baseline: 1.2729x; 1.0364x over previous
#include <cuda_runtime.h>
#include <cuda_fp16.h>
#include <cstdint>

#define NB     16
#define NMEDIA 4096
#define NLAT   64
#define NKV    4160
#define DIM    1024
#define INNER  1024
#define NHEADS 16
#define DHEAD  64
#define SPLIT  5
#define TILES_PER 13   // 65 K-tiles of 64 / SPLIT

// ---------------- scratch (static device globals; no runtime allocation) ----------------
__device__ __half g_kvin [(size_t)NB*NKV*DIM];      // layernormed [x ; latents]  (fp16)
__device__ __half g_lat16[(size_t)NB*NLAT*DIM];     // layernormed latents        (fp16)
__device__ __half g_q16  [(size_t)NB*NLAT*INNER];   // q * scale                  (fp16)
__device__ __half g_kv16 [(size_t)NB*NKV*2*INNER];  // [k | v] output             (fp16)
__device__ __half g_ao16 [(size_t)NB*NLAT*INNER];   // attention output           (fp16)
__device__ __half g_wq16 [(size_t)DIM*INNER];       // Wq fp16
__device__ __half g_wkv16[(size_t)DIM*2*INNER];     // Wkv fp16 [K][N]
__device__ __half g_wout16[(size_t)INNER*DIM];      // Wout fp16
__device__ float  g_opart[(size_t)SPLIT*NB*NLAT*INNER];    // unnormalized partial O
__device__ float  g_mlp  [(size_t)SPLIT*NB*NLAT*NHEADS*2]; // (m, l)

// ---------------- helpers ----------------
__device__ __forceinline__ void cp_async16(uint32_t smem_dst, const void* gsrc) {
    asm volatile("cp.async.cg.shared.global [%0], [%1], 16;\n" :: "r"(smem_dst), "l"(gsrc));
}
__device__ __forceinline__ void cp_commit() { asm volatile("cp.async.commit_group;\n" ::); }
__device__ __forceinline__ void cp_wait2()  { asm volatile("cp.async.wait_group 2;\n" ::); }
__device__ __forceinline__ void cp_wait1()  { asm volatile("cp.async.wait_group 1;\n" ::); }
__device__ __forceinline__ void cp_wait0()  { asm volatile("cp.async.wait_group 0;\n" ::); }

// ---------------- weight conversion fp32 -> fp16 ----------------
__global__ void cvt_weights(const float* __restrict__ Wq,
                            const float* __restrict__ Wkv,
                            const float* __restrict__ Wout) {
    int i = blockIdx.x * blockDim.x + threadIdx.x;
    const int n1 = DIM*INNER;
    const int n2 = DIM*2*INNER;
    if (i < n1) g_wq16[i] = __float2half(Wq[i]);
    int j = i - n1;
    if (j >= 0 && j < n2) g_wkv16[j] = __float2half(Wkv[j]);
    int k = j - n2;
    if (k >= 0 && k < INNER*DIM) g_wout16[k] = __float2half(Wout[k]);
}

// ---------------- fused layernorm (x and latents), writes fp16 ----------------
__global__ void __launch_bounds__(256) ln_kernel(
    const float* __restrict__ x, const float* __restrict__ lat,
    const float* __restrict__ gm, const float* __restrict__ bm,
    const float* __restrict__ gl, const float* __restrict__ bl)
{
    int r  = blockIdx.x;
    int b  = r / NKV;
    int jj = r - b * NKV;
    bool isl = (jj >= NMEDIA);
    const float* src = isl ? lat + ((size_t)b*NLAT + (jj - NMEDIA))*DIM
                           : x   + ((size_t)b*NMEDIA + jj)*DIM;
    const float* g  = isl ? gl : gm;
    const float* be = isl ? bl : bm;

    int t = threadIdx.x;
    float v[4];
    float s = 0.f, s2 = 0.f;
#pragma unroll
    for (int k = 0; k < 4; k++) {
        float u = src[t + 256*k];
        v[k] = u; s += u; s2 += u*u;
    }
#pragma unroll
    for (int o = 16; o; o >>= 1) {
        s  += __shfl_xor_sync(0xffffffffu, s,  o);
        s2 += __shfl_xor_sync(0xffffffffu, s2, o);
    }
    __shared__ float rs[8], rs2[8];
    if ((t & 31) == 0) { rs[t >> 5] = s; rs2[t >> 5] = s2; }
    __syncthreads();
    float ts = 0.f, ts2 = 0.f;
#pragma unroll
    for (int w = 0; w < 8; w++) { ts += rs[w]; ts2 += rs2[w]; }
    float mu  = ts * (1.f/DIM);
    float inv = rsqrtf(ts2 * (1.f/DIM) - mu*mu + 1e-5f);

    __half* d1 = g_kvin + (size_t)r * DIM;
    __half* d2 = isl ? g_lat16 + ((size_t)b*NLAT + (jj - NMEDIA))*DIM : nullptr;
#pragma unroll
    for (int k = 0; k < 4; k++) {
        int c = t + 256*k;
        __half hv = __float2half((v[k] - mu) * inv * g[c] + be[c]);
        d1[c] = hv;
        if (d2) d2[c] = hv;
    }
}

// ================ kv GEMM: BM=128 BN=256 BK=64, 4-stage cp.async, mma.sync ================
#define KBM 128
#define KBN 256
#define KBK 64
#define KAS 72      // A smem row stride (halves)
#define KBS 264     // B smem row stride (halves)
#define KV_STAGE_A (KBM*KAS)              // halves
#define KV_STAGE_B (KBK*KBS)
#define KV_SMEM    (4*(KV_STAGE_A + KV_STAGE_B)*(int)sizeof(__half))   // 208896 B

__global__ void __launch_bounds__(256, 1) gemm_kv256() {
    extern __shared__ __half smh[];
    __half* As = smh;                      // [4][KBM][KAS]
    __half* Bs = smh + 4*KV_STAGE_A;       // [4][KBK][KBS]

    const int tid  = threadIdx.x;
    const int warp = tid >> 5, lane = tid & 31;
    const int wm = (warp & 1) * 64;
    const int wn = (warp >> 1) * 64;
    const int bn0 = blockIdx.x * KBN;
    const int bm0 = blockIdx.y * KBM;
    const int K = DIM, N = 2*INNER;

    float acc[4][8][4];
#pragma unroll
    for (int a = 0; a < 4; a++)
#pragma unroll
        for (int b = 0; b < 8; b++)
#pragma unroll
            for (int c = 0; c < 4; c++) acc[a][b][c] = 0.f;

    const uint32_t sA = (uint32_t)__cvta_generic_to_shared(As);
    const uint32_t sB = (uint32_t)__cvta_generic_to_shared(Bs);
    const int arow = tid >> 1, acb = (tid & 1) * 32;   // A: 128 rows x 64 cols
    const int brow = tid >> 2, bcb = (tid & 3) * 64;   // B: 64 rows x 256 cols

    auto issue = [&](int t, int st) {
        const int k0 = t * KBK;
        const __half* ga = g_kvin + (size_t)(bm0 + arow) * K + k0 + acb;
        uint32_t da = sA + ((st*KBM + arow)*KAS + acb) * 2;
#pragma unroll
        for (int c = 0; c < 4; c++) cp_async16(da + c*16, ga + c*8);
        const __half* gb = g_wkv16 + (size_t)(k0 + brow) * N + bn0 + bcb;
        uint32_t db = sB + ((st*KBK + brow)*KBS + bcb) * 2;
#pragma unroll
        for (int c = 0; c < 8; c++) cp_async16(db + c*16, gb + c*8);
    };

    issue(0, 0); cp_commit();
    issue(1, 1); cp_commit();
    issue(2, 2); cp_commit();

    const int NT = K / KBK;   // 16
    for (int t = 0; t < NT; t++) {
        const int st = t & 3;
        if (t <= NT - 3)      cp_wait2();
        else if (t == NT - 2) cp_wait1();
        else                  cp_wait0();
        __syncthreads();

        const __half* as = As + (size_t)st * KV_STAGE_A;
        const __half* bs = Bs + (size_t)st * KV_STAGE_B;

#pragma unroll
        for (int kc = 0; kc < KBK; kc += 16) {
            uint32_t af[4][4], bf[8][2];
#pragma unroll
            for (int mf = 0; mf < 4; mf++) {
                uint32_t ad = (uint32_t)__cvta_generic_to_shared(
                    &as[(wm + mf*16 + (lane & 15))*KAS + kc + ((lane >> 4) << 3)]);
                asm volatile("ldmatrix.sync.aligned.m8n8.x4.shared.b16 {%0,%1,%2,%3}, [%4];"
                    : "=r"(af[mf][0]), "=r"(af[mf][1]), "=r"(af[mf][2]), "=r"(af[mf][3])
                    : "r"(ad));
            }
#pragma unroll
            for (int nq = 0; nq < 4; nq++) {
                uint32_t bd = (uint32_t)__cvta_generic_to_shared(
                    &bs[(kc + (lane & 15))*KBS + wn + nq*16 + ((lane >> 4) << 3)]);
                asm volatile("ldmatrix.sync.aligned.m8n8.x4.trans.shared.b16 {%0,%1,%2,%3}, [%4];"
                    : "=r"(bf[2*nq][0]), "=r"(bf[2*nq][1]),
                      "=r"(bf[2*nq+1][0]), "=r"(bf[2*nq+1][1])
                    : "r"(bd));
            }
#pragma unroll
            for (int mf = 0; mf < 4; mf++)
#pragma unroll
                for (int nf = 0; nf < 8; nf++) {
                    asm volatile(
                        "mma.sync.aligned.m16n8k16.row.col.f32.f16.f16.f32 "
                        "{%0,%1,%2,%3}, {%4,%5,%6,%7}, {%8,%9}, {%0,%1,%2,%3};"
                        : "+f"(acc[mf][nf][0]), "+f"(acc[mf][nf][1]),
                          "+f"(acc[mf][nf][2]), "+f"(acc[mf][nf][3])
                        : "r"(af[mf][0]), "r"(af[mf][1]), "r"(af[mf][2]), "r"(af[mf][3]),
                          "r"(bf[nf][0]), "r"(bf[nf][1]));
                }
        }
        if (t + 3 < NT) { issue(t + 3, (t + 3) & 3); cp_commit(); }
    }

    const int grp = lane >> 2, tig = lane & 3;
#pragma unroll
    for (int mf = 0; mf < 4; mf++)
#pragma unroll
        for (int nf = 0; nf < 8; nf++) {
            int row = bm0 + wm + mf*16 + grp;
            int col = bn0 + wn + nf*8 + tig*2;
            *(__half2*)&g_kv16[(size_t)row * N + col] =
                __floats2half2_rn(acc[mf][nf][0], acc[mf][nf][1]);
            *(__half2*)&g_kv16[(size_t)(row + 8) * N + col] =
                __floats2half2_rn(acc[mf][nf][2], acc[mf][nf][3]);
        }
}

// ---------------- double-buffered mma.sync GEMM (q and out GEMMs, small) ----------------
#define BM 128
#define BN 128
#define BKG 64
#define AS_STRIDE 72
#define BS_STRIDE 136
#define GEMM_SMEM ((2*BM*AS_STRIDE + 2*BKG*BS_STRIDE) * (int)sizeof(__half))

template<typename OutT>
__global__ void __launch_bounds__(256) gemm_db(
    const __half* __restrict__ A, const __half* __restrict__ Bmat,
    OutT* __restrict__ C, int M, int N, int K, float alpha)
{
    extern __shared__ __half smh[];
    __half* As = smh;
    __half* Bs = smh + 2*BM*AS_STRIDE;

    const int tid  = threadIdx.x;
    const int warp = tid >> 5, lane = tid & 31;
    const int wm = (warp & 1) * 64;
    const int wn = (warp >> 1) * 32;
    const int bm0 = blockIdx.y * BM;
    const int bn0 = blockIdx.x * BN;

    float acc[4][4][4];
#pragma unroll
    for (int a = 0; a < 4; a++)
#pragma unroll
        for (int b = 0; b < 4; b++)
#pragma unroll
            for (int c = 0; c < 4; c++) acc[a][b][c] = 0.f;

    const int arow = tid >> 1, acb = (tid & 1) * 32;
    const int brow = tid >> 2, bcb = (tid & 3) * 32;
    const uint32_t sA = (uint32_t)__cvta_generic_to_shared(As);
    const uint32_t sB = (uint32_t)__cvta_generic_to_shared(Bs);

    auto issue = [&](int k0, int st) {
        const __half* ga = A + (size_t)(bm0 + arow) * K + (k0 + acb);
        uint32_t da = sA + ((st*BM + arow)*AS_STRIDE + acb) * 2;
#pragma unroll
        for (int c = 0; c < 4; c++) cp_async16(da + c*16, ga + c*8);
        const __half* gb = Bmat + (size_t)(k0 + brow) * N + (bn0 + bcb);
        uint32_t db = sB + ((st*BKG + brow)*BS_STRIDE + bcb) * 2;
#pragma unroll
        for (int c = 0; c < 4; c++) cp_async16(db + c*16, gb + c*8);
    };

    issue(0, 0);
    cp_commit();

    int stage = 0;
    for (int k0 = 0; k0 < K; k0 += BKG) {
        if (k0 + BKG < K) { issue(k0 + BKG, stage ^ 1); cp_commit(); cp_wait1(); }
        else              { cp_wait0(); }
        __syncthreads();

        const __half* as = As + (size_t)stage * BM * AS_STRIDE;
        const __half* bs = Bs + (size_t)stage * BKG * BS_STRIDE;

#pragma unroll
        for (int kc = 0; kc < BKG; kc += 16) {
            uint32_t af[4][4], bf[4][2];
#pragma unroll
            for (int mf = 0; mf < 4; mf++) {
                uint32_t ad = (uint32_t)__cvta_generic_to_shared(
                    &as[(wm + mf*16 + (lane & 15))*AS_STRIDE + kc + ((lane >> 4) << 3)]);
                asm volatile("ldmatrix.sync.aligned.m8n8.x4.shared.b16 {%0,%1,%2,%3}, [%4];"
                    : "=r"(af[mf][0]), "=r"(af[mf][1]), "=r"(af[mf][2]), "=r"(af[mf][3])
                    : "r"(ad));
            }
#pragma unroll
            for (int nf = 0; nf < 4; nf++) {
                uint32_t bd = (uint32_t)__cvta_generic_to_shared(
                    &bs[(kc + (lane & 15))*BS_STRIDE + wn + nf*8]);
                asm volatile("ldmatrix.sync.aligned.m8n8.x2.trans.shared.b16 {%0,%1}, [%2];"
                    : "=r"(bf[nf][0]), "=r"(bf[nf][1]) : "r"(bd));
            }
#pragma unroll
            for (int mf = 0; mf < 4; mf++)
#pragma unroll
                for (int nf = 0; nf < 4; nf++) {
                    asm volatile(
                        "mma.sync.aligned.m16n8k16.row.col.f32.f16.f16.f32 "
                        "{%0,%1,%2,%3}, {%4,%5,%6,%7}, {%8,%9}, {%0,%1,%2,%3};"
                        : "+f"(acc[mf][nf][0]), "+f"(acc[mf][nf][1]),
                          "+f"(acc[mf][nf][2]), "+f"(acc[mf][nf][3])
                        : "r"(af[mf][0]), "r"(af[mf][1]), "r"(af[mf][2]), "r"(af[mf][3]),
                          "r"(bf[nf][0]), "r"(bf[nf][1]));
                }
        }
        __syncthreads();
        stage ^= 1;
    }

    const int grp = lane >> 2, tig = lane & 3;
#pragma unroll
    for (int mf = 0; mf < 4; mf++)
#pragma unroll
        for (int nf = 0; nf < 4; nf++) {
            int row = bm0 + wm + mf*16 + grp;
            int col = bn0 + wn + nf*8 + tig*2;
            if constexpr (sizeof(OutT) == 2) {
                *(__half2*)&C[(size_t)row * N + col] =
                    __floats2half2_rn(acc[mf][nf][0]*alpha, acc[mf][nf][1]*alpha);
                *(__half2*)&C[(size_t)(row + 8) * N + col] =
                    __floats2half2_rn(acc[mf][nf][2]*alpha, acc[mf][nf][3]*alpha);
            } else {
                *(float2*)&C[(size_t)row * N + col] =
                    make_float2(acc[mf][nf][0]*alpha, acc[mf][nf][1]*alpha);
                *(float2*)&C[(size_t)(row + 8) * N + col] =
                    make_float2(acc[mf][nf][2]*alpha, acc[mf][nf][3]*alpha);
            }
        }
}

// ---------------- tensor-core flash attention, split-KV ----------------
#define QS_STR 72

__global__ void __launch_bounds__(128) attn_mma_kernel() {
    __shared__ __half Qs[64][QS_STR];
    __shared__ __half Ks[2][64][QS_STR];
    __shared__ __half Vs[2][64][QS_STR];

    const int b = blockIdx.x, h = blockIdx.y, sp = blockIdx.z;
    const int tid = threadIdx.x;
    const int warp = tid >> 5, lane = tid & 31;
    const int grp = lane >> 2, tig = lane & 3;

    {
        int row = tid >> 1, cb = (tid & 1) * 32;
        const __half* q = g_q16 + ((size_t)(b*NLAT + row))*INNER + h*DHEAD + cb;
#pragma unroll
        for (int c = 0; c < 4; c++)
            *(uint4*)&Qs[row][cb + c*8] = *(const uint4*)(q + c*8);
    }
    __syncthreads();

    uint32_t qf[4][4];
#pragma unroll
    for (int kk = 0; kk < 4; kk++) {
        uint32_t ad = (uint32_t)__cvta_generic_to_shared(
            &Qs[warp*16 + (lane & 15)][kk*16 + ((lane >> 4) << 3)]);
        asm volatile("ldmatrix.sync.aligned.m8n8.x4.shared.b16 {%0,%1,%2,%3}, [%4];"
            : "=r"(qf[kk][0]), "=r"(qf[kk][1]), "=r"(qf[kk][2]), "=r"(qf[kk][3])
            : "r"(ad));
    }

    const uint32_t sK = (uint32_t)__cvta_generic_to_shared(&Ks[0][0][0]);
    const uint32_t sV = (uint32_t)__cvta_generic_to_shared(&Vs[0][0][0]);
    const int ldr = tid >> 1, ldcb = (tid & 1) * 32;

    auto issue_kv = [&](int jt, int st) {
        size_t gbase = ((size_t)(b*NKV + jt*64 + ldr)) * (2*INNER) + h*DHEAD + ldcb;
        uint32_t dk = sK + ((st*64 + ldr)*QS_STR + ldcb) * 2;
        uint32_t dv = sV + ((st*64 + ldr)*QS_STR + ldcb) * 2;
#pragma unroll
        for (int c = 0; c < 4; c++) {
            cp_async16(dk + c*16, g_kv16 + gbase + c*8);
            cp_async16(dv + c*16, g_kv16 + gbase + INNER + c*8);
        }
    };

    const int t0 = sp * TILES_PER;
    issue_kv(t0, 0);
    cp_commit();

    float m0 = -1e30f, m1 = -1e30f, l0 = 0.f, l1 = 0.f;
    float of[8][4];
#pragma unroll
    for (int nf = 0; nf < 8; nf++)
#pragma unroll
        for (int c = 0; c < 4; c++) of[nf][c] = 0.f;

    int stage = 0;
    for (int jt = 0; jt < TILES_PER; jt++) {
        if (jt + 1 < TILES_PER) { issue_kv(t0 + jt + 1, stage ^ 1); cp_commit(); cp_wait1(); }
        else                    { cp_wait0(); }
        __syncthreads();

        float sf[8][4];
#pragma unroll
        for (int nf = 0; nf < 8; nf++) {
            sf[nf][0] = sf[nf][1] = sf[nf][2] = sf[nf][3] = 0.f;
#pragma unroll
            for (int kk = 0; kk < 4; kk++) {
                uint32_t bd = (uint32_t)__cvta_generic_to_shared(
                    &Ks[stage][nf*8 + (lane & 7)][kk*16 + ((lane >> 3) & 1) * 8]);
                uint32_t b0, b1;
                asm volatile("ldmatrix.sync.aligned.m8n8.x2.shared.b16 {%0,%1}, [%2];"
                    : "=r"(b0), "=r"(b1) : "r"(bd));
                asm volatile(
                    "mma.sync.aligned.m16n8k16.row.col.f32.f16.f16.f32 "
                    "{%0,%1,%2,%3}, {%4,%5,%6,%7}, {%8,%9}, {%0,%1,%2,%3};"
                    : "+f"(sf[nf][0]), "+f"(sf[nf][1]), "+f"(sf[nf][2]), "+f"(sf[nf][3])
                    : "r"(qf[kk][0]), "r"(qf[kk][1]), "r"(qf[kk][2]), "r"(qf[kk][3]),
                      "r"(b0), "r"(b1));
            }
        }

        float mx0 = -1e30f, mx1 = -1e30f;
#pragma unroll
        for (int nf = 0; nf < 8; nf++) {
            mx0 = fmaxf(mx0, fmaxf(sf[nf][0], sf[nf][1]));
            mx1 = fmaxf(mx1, fmaxf(sf[nf][2], sf[nf][3]));
        }
        mx0 = fmaxf(mx0, __shfl_xor_sync(0xffffffffu, mx0, 1));
        mx0 = fmaxf(mx0, __shfl_xor_sync(0xffffffffu, mx0, 2));
        mx1 = fmaxf(mx1, __shfl_xor_sync(0xffffffffu, mx1, 1));
        mx1 = fmaxf(mx1, __shfl_xor_sync(0xffffffffu, mx1, 2));

        float mn0 = fmaxf(m0, mx0), mn1 = fmaxf(m1, mx1);
        float sc0 = __expf(m0 - mn0), sc1 = __expf(m1 - mn1);

        uint32_t pa[8], pb[8];
        float ls0 = 0.f, ls1 = 0.f;
#pragma unroll
        for (int nf = 0; nf < 8; nf++) {
            float p0 = __expf(sf[nf][0] - mn0);
            float p1 = __expf(sf[nf][1] - mn0);
            float p2 = __expf(sf[nf][2] - mn1);
            float p3 = __expf(sf[nf][3] - mn1);
            ls0 += p0 + p1; ls1 += p2 + p3;
            __half2 ha = __floats2half2_rn(p0, p1);
            __half2 hb = __floats2half2_rn(p2, p3);
            pa[nf] = *(uint32_t*)&ha;
            pb[nf] = *(uint32_t*)&hb;
        }
        ls0 += __shfl_xor_sync(0xffffffffu, ls0, 1);
        ls0 += __shfl_xor_sync(0xffffffffu, ls0, 2);
        ls1 += __shfl_xor_sync(0xffffffffu, ls1, 1);
        ls1 += __shfl_xor_sync(0xffffffffu, ls1, 2);

        l0 = l0 * sc0 + ls0;
        l1 = l1 * sc1 + ls1;
        m0 = mn0; m1 = mn1;
#pragma unroll
        for (int nf = 0; nf < 8; nf++) {
            of[nf][0] *= sc0; of[nf][1] *= sc0;
            of[nf][2] *= sc1; of[nf][3] *= sc1;
        }

#pragma unroll
        for (int nf = 0; nf < 8; nf++) {
#pragma unroll
            for (int kk = 0; kk < 4; kk++) {
                uint32_t bd = (uint32_t)__cvta_generic_to_shared(
                    &Vs[stage][kk*16 + (lane & 15)][nf*8]);
                uint32_t b0, b1;
                asm volatile("ldmatrix.sync.aligned.m8n8.x2.trans.shared.b16 {%0,%1}, [%2];"
                    : "=r"(b0), "=r"(b1) : "r"(bd));
                asm volatile(
                    "mma.sync.aligned.m16n8k16.row.col.f32.f16.f16.f32 "
                    "{%0,%1,%2,%3}, {%4,%5,%6,%7}, {%8,%9}, {%0,%1,%2,%3};"
                    : "+f"(of[nf][0]), "+f"(of[nf][1]), "+f"(of[nf][2]), "+f"(of[nf][3])
                    : "r"(pa[2*kk]), "r"(pb[2*kk]), "r"(pa[2*kk+1]), "r"(pb[2*kk+1]),
                      "r"(b0), "r"(b1));
            }
        }
        __syncthreads();
        stage ^= 1;
    }

    // ---- partial epilogue: unnormalized O (fp32) + (m, l) ----
    const int row0g = b*NLAT + warp*16 + grp;
    float* op0 = g_opart + ((size_t)sp*NB*NLAT + row0g)*INNER + h*DHEAD;
    float* op1 = op0 + (size_t)8*INNER;
#pragma unroll
    for (int nf = 0; nf < 8; nf++) {
        int col = nf*8 + tig*2;
        *(float2*)&op0[col] = make_float2(of[nf][0], of[nf][1]);
        *(float2*)&op1[col] = make_float2(of[nf][2], of[nf][3]);
    }
    if (tig == 0) {
        size_t i0 = (((size_t)sp*NB*NLAT + row0g)*NHEADS + h)*2;
        g_mlp[i0]   = m0; g_mlp[i0+1] = l0;
        size_t i1 = (((size_t)sp*NB*NLAT + row0g + 8)*NHEADS + h)*2;
        g_mlp[i1]   = m1; g_mlp[i1+1] = l1;
    }
}

// ---------------- split-KV combine ----------------
__global__ void __launch_bounds__(256) attn_combine() {
    int idx = blockIdx.x * 256 + threadIdx.x;     // 0 .. 512K-1, 2 cols each
    int row = idx >> 9;
    int c2  = (idx & 511) * 2;
    int h   = c2 >> 6;

    float ms[SPLIT], ls[SPLIT];
    float M = -1e30f;
#pragma unroll
    for (int s = 0; s < SPLIT; s++) {
        size_t i = (((size_t)s*NB*NLAT + row)*NHEADS + h)*2;
        ms[s] = g_mlp[i]; ls[s] = g_mlp[i+1];
        M = fmaxf(M, ms[s]);
    }
    float L = 0.f, o0 = 0.f, o1 = 0.f;
#pragma unroll
    for (int s = 0; s < SPLIT; s++) {
        float w = __expf(ms[s] - M);
        L += ls[s] * w;
        float2 v = *(const float2*)&g_opart[((size_t)s*NB*NLAT + row)*INNER + c2];
        o0 += v.x * w; o1 += v.y * w;
    }
    float inv = 1.f / L;
    *(__half2*)&g_ao16[(size_t)row*INNER + c2] = __floats2half2_rn(o0*inv, o1*inv);
}

// ---------------- launch ----------------
extern "C" void kernel_launch(void* const* d_in, const int* in_sizes, int n_in,
                              void* d_out, int out_size) {
    const float* x    = (const float*)d_in[0];
    const float* lat  = (const float*)d_in[1];
    const float* gm   = (const float*)d_in[2];
    const float* bm   = (const float*)d_in[3];
    const float* gl   = (const float*)d_in[4];
    const float* bl   = (const float*)d_in[5];
    const float* Wq   = (const float*)d_in[6];
    const float* Wkv  = (const float*)d_in[7];
    const float* Wout = (const float*)d_in[8];
    float* out = (float*)d_out;

    void *p_lat, *p_q, *p_ao, *p_wq, *p_wout;
    cudaGetSymbolAddress(&p_lat,  g_lat16);
    cudaGetSymbolAddress(&p_q,    g_q16);
    cudaGetSymbolAddress(&p_ao,   g_ao16);
    cudaGetSymbolAddress(&p_wq,   g_wq16);
    cudaGetSymbolAddress(&p_wout, g_wout16);

    static bool attr_done = false;
    if (!attr_done) {
        cudaFuncSetAttribute(gemm_db<__half>, cudaFuncAttributeMaxDynamicSharedMemorySize, GEMM_SMEM);
        cudaFuncSetAttribute(gemm_db<float>,  cudaFuncAttributeMaxDynamicSharedMemorySize, GEMM_SMEM);
        cudaFuncSetAttribute(gemm_kv256,      cudaFuncAttributeMaxDynamicSharedMemorySize, KV_SMEM);
        attr_done = true;
    }

    // 1. weights fp32 -> fp16
    cvt_weights<<<(4*1024*1024 + 255)/256, 256>>>(Wq, Wkv, Wout);

    // 2. layernorm
    ln_kernel<<<NB*NKV, 256>>>(x, lat, gm, bm, gl, bl);

    // 3. q = lat_ln @ Wq * d^-0.5
    {
        dim3 grid(INNER/BN, (NB*NLAT)/BM);
        gemm_db<__half><<<grid, 256, GEMM_SMEM>>>((const __half*)p_lat, (const __half*)p_wq,
                                                  (__half*)p_q, NB*NLAT, INNER, DIM, 0.125f);
    }

    // 4. kv GEMM (wide-tile, 4-stage pipeline)
    {
        dim3 grid((2*INNER)/KBN, (NB*NKV)/KBM);
        gemm_kv256<<<grid, 256, KV_SMEM>>>();
    }

    // 5. attention (split-KV) + combine
    {
        dim3 grid(NB, NHEADS, SPLIT);
        attn_mma_kernel<<<grid, 128>>>();
        attn_combine<<<(NB*NLAT*INNER/2 + 255)/256, 256>>>();
    }

    // 6. out = ao @ Wout -> d_out (fp32)
    {
        dim3 grid(DIM/BN, (NB*NLAT)/BM);
        gemm_db<float><<<grid, 256, GEMM_SMEM>>>((const __half*)p_ao, (const __half*)p_wout,
                                                 out, NB*NLAT, DIM, INNER, 1.0f);
    }
}